// round 1
// baseline (speedup 1.0000x reference)
#include <cuda_runtime.h>
#include <cuda_bf16.h>
#include <math.h>

// Problem constants
#define BZ 32
#define SZ 128
#define HZ 768
#define NC 14     // channels: 0=wh, 1=wt, 2-5=wi[:,j], 6-9=we[0:H,j], 10-13=we[H:2H,j]
#define MM 8      // max span width
#define MH_ 6
#define KK 4      // KH == KT == 4

// scratch: per-row dots [B][S][NC]
__device__ float g_dots[BZ * SZ * NC];

// ---------------------------------------------------------------------------
// Kernel 1: 14-column GEMV over embedding rows.
// grid (BZ, 4), block 256. Each warp handles 4 consecutive rows so each
// shared weight load feeds 4 FMAs (amortizes LDS crossbar vs FMA pipe).
// ---------------------------------------------------------------------------
__global__ __launch_bounds__(256) void k_dots(
    const float* __restrict__ emb,
    const float* __restrict__ wh,
    const float* __restrict__ wt,
    const float* __restrict__ wi,
    const float* __restrict__ we)
{
    __shared__ float shw[NC][HZ];
    const int b = blockIdx.x;
    const int tid = threadIdx.x;

    // cooperative weight load into shared
    for (int idx = tid; idx < NC * HZ; idx += 256) {
        int c = idx / HZ, h = idx - c * HZ;
        float v;
        if (c == 0)      v = wh[h];
        else if (c == 1) v = wt[h];
        else if (c < 6)  v = wi[h * 4 + (c - 2)];
        else if (c < 10) v = we[h * 4 + (c - 6)];
        else             v = we[(HZ + h) * 4 + (c - 10)];
        shw[c][h] = v;
    }
    __syncthreads();

    const int warp = tid >> 5, lane = tid & 31;
    const int r0 = blockIdx.y * 32 + warp * 4;   // 4 rows per warp
    const float* e0 = emb + ((size_t)b * SZ + r0) * HZ;

    float acc[4][NC];
#pragma unroll
    for (int r = 0; r < 4; r++)
#pragma unroll
        for (int c = 0; c < NC; c++) acc[r][c] = 0.f;

    for (int h = lane; h < HZ; h += 32) {
        float e0v = e0[h];
        float e1v = e0[HZ + h];
        float e2v = e0[2 * HZ + h];
        float e3v = e0[3 * HZ + h];
#pragma unroll
        for (int c = 0; c < NC; c++) {
            float w = shw[c][h];
            acc[0][c] += e0v * w;
            acc[1][c] += e1v * w;
            acc[2][c] += e2v * w;
            acc[3][c] += e3v * w;
        }
    }

    // warp reductions
#pragma unroll
    for (int r = 0; r < 4; r++)
#pragma unroll
        for (int c = 0; c < NC; c++)
#pragma unroll
            for (int off = 16; off > 0; off >>= 1)
                acc[r][c] += __shfl_xor_sync(0xFFFFFFFFu, acc[r][c], off);

    if (lane == 0) {
#pragma unroll
        for (int r = 0; r < 4; r++) {
            float* dst = &g_dots[((size_t)b * SZ + (r0 + r)) * NC];
#pragma unroll
            for (int c = 0; c < NC; c++) dst[c] = acc[r][c];
        }
    }
}

// ---------------------------------------------------------------------------
// Kernel 2: per-batch prefix sums, span scores, top-k, logits, outputs.
// grid BZ, block 256.
// ---------------------------------------------------------------------------
__global__ __launch_bounds__(256) void k_main(
    const int* __restrict__ mask,
    const float* __restrict__ bh_,
    const float* __restrict__ bt_,
    const float* __restrict__ bi,
    const float* __restrict__ be,
    float* __restrict__ out)
{
    __shared__ float pref[NC][SZ + 1];
    __shared__ float sc_h[MM * SZ];
    __shared__ float sc_t[MM * SZ];
    __shared__ unsigned long long red[256];
    __shared__ float topv_t[KK]; __shared__ int topi_t[KK];
    __shared__ float topv_h[KK]; __shared__ int topi_h[KK];
    __shared__ int s_len;

    const int b = blockIdx.x;
    const int tid = threadIdx.x;
    const int warp = tid >> 5, lane = tid & 31;

    if (tid == 0) s_len = 0;
    if (tid < NC) pref[tid][0] = 0.f;
    __syncthreads();

    // load per-row dots (coalesced) and sentence length
    for (int idx = tid; idx < SZ * NC; idx += 256) {
        int s = idx / NC, c = idx - s * NC;
        pref[c][s + 1] = g_dots[((size_t)b * SZ + s) * NC + c];
    }
    if (tid < SZ) {
        int v = mask[b * SZ + tid];
#pragma unroll
        for (int off = 16; off > 0; off >>= 1)
            v += __shfl_xor_sync(0xFFFFFFFFu, v, off);
        if (lane == 0) atomicAdd(&s_len, v);
    }
    __syncthreads();

    // prefix sums over S for all NC channels: one warp per channel,
    // 4 values per lane + shuffle scan of lane totals.
    for (int c = warp; c < NC; c += 8) {
        float v0 = pref[c][lane * 4 + 1];
        float v1 = pref[c][lane * 4 + 2];
        float v2 = pref[c][lane * 4 + 3];
        float v3 = pref[c][lane * 4 + 4];
        v1 += v0; v2 += v1; v3 += v2;
        float tot = v3, x = tot;
#pragma unroll
        for (int off = 1; off < 32; off <<= 1) {
            float y = __shfl_up_sync(0xFFFFFFFFu, x, off);
            if (lane >= off) x += y;
        }
        float excl = x - tot;
        pref[c][lane * 4 + 1] = v0 + excl;
        pref[c][lane * 4 + 2] = v1 + excl;
        pref[c][lane * 4 + 3] = v2 + excl;
        pref[c][lane * 4 + 4] = v3 + excl;
    }
    __syncthreads();

    const int len = s_len;
    const float bhv = bh_[0], btv = bt_[0];

    // span scores + write hs/ts outputs
    // out layout (floats): implicit[0,512) explicit[512,2560) hs[2560,35328) ts[35328,68096)
    float* out_hs = out + 2560 + (size_t)b * (MM * SZ);
    float* out_ts = out + 35328 + (size_t)b * (MM * SZ);
    for (int idx = tid; idx < MM * SZ; idx += 256) {
        int m = idx >> 7, s = idx & 127;
        bool tv = (s + m) < len;             // width_idx m < MT=8 always
        bool hv = tv && (m < MH_);
        float w = (float)(m + 1);
        float dh = (pref[0][s + m + 1] - pref[0][s]) / w;
        float dt = (pref[1][s + m + 1] - pref[1][s]) / w;
        float vh = hv ? 1.f / (1.f + expf(-(dh + bhv))) : -1.f;
        float vt = tv ? 1.f / (1.f + expf(-(dt + btv))) : -1.f;
        sc_h[idx] = vh; sc_t[idx] = vt;
        out_hs[idx] = vh; out_ts[idx] = vt;
    }
    __syncthreads();

    // iterative top-4 argmax with jax tie-break (max value, then min index)
    // key = ordered-float(v) << 32 | (0xFFFFFFFF - idx)
    for (int which = 0; which < 2; which++) {
        float* sc = which ? sc_h : sc_t;
        float* tv = which ? topv_h : topv_t;
        int*   ti = which ? topi_h : topi_t;
        for (int k = 0; k < KK; k++) {
            unsigned long long best = 0ull;
            for (int idx = tid; idx < MM * SZ; idx += 256) {
                unsigned u = __float_as_uint(sc[idx]);
                u = (u & 0x80000000u) ? ~u : (u | 0x80000000u);
                unsigned long long key =
                    ((unsigned long long)u << 32) | (unsigned)(0xFFFFFFFFu - idx);
                best = best > key ? best : key;
            }
            red[tid] = best;
            __syncthreads();
#pragma unroll
            for (int off = 128; off > 0; off >>= 1) {
                if (tid < off) {
                    unsigned long long o = red[tid + off];
                    if (o > red[tid]) red[tid] = o;
                }
                __syncthreads();
            }
            if (tid == 0) {
                int idx = (int)(0xFFFFFFFFu - (unsigned)(red[0] & 0xFFFFFFFFull));
                tv[k] = sc[idx];
                ti[k] = idx;
                sc[idx] = -3.0f;   // below all valid & invalid scores
            }
            __syncthreads();
        }
    }

    // logits straight from prefix sums
    if (tid < 64) {
        // explicit: k=holder, i=target, j=class
        int k = tid >> 4, i = (tid >> 2) & 3, j = tid & 3;
        float vhk = topv_h[k], vti = topv_t[i];
        float val = be[j];
        if (vhk > 0.f && vti > 0.f) {
            int ih = topi_h[k], it = topi_t[i];
            int mh = ih >> 7, sh = ih & 127;
            int mt = it >> 7, st = it & 127;
            val += (pref[6 + j][sh + mh + 1] - pref[6 + j][sh]) / (float)(mh + 1)
                 + (pref[10 + j][st + mt + 1] - pref[10 + j][st]) / (float)(mt + 1);
        }
        out[512 + (size_t)b * 64 + tid] = val;
    } else if (tid < 80) {
        // implicit: i=target, j=class
        int t2 = tid - 64;
        int i = t2 >> 2, j = t2 & 3;
        float vti = topv_t[i];
        float val = bi[j];
        if (vti > 0.f) {
            int it = topi_t[i];
            int m = it >> 7, s = it & 127;
            val += (pref[2 + j][s + m + 1] - pref[2 + j][s]) / (float)(m + 1);
        }
        out[(size_t)b * 16 + t2] = val;
    }
}

// ---------------------------------------------------------------------------
// Launch. Input order (metadata): embedding, mask, wh, bh, wt, bt, wi, bi, we, be
// ---------------------------------------------------------------------------
extern "C" void kernel_launch(void* const* d_in, const int* in_sizes, int n_in,
                              void* d_out, int out_size)
{
    const float* emb = (const float*)d_in[0];
    const int*   msk = (const int*)d_in[1];
    const float* wh  = (const float*)d_in[2];
    const float* bh  = (const float*)d_in[3];
    const float* wt  = (const float*)d_in[4];
    const float* bt  = (const float*)d_in[5];
    const float* wi  = (const float*)d_in[6];
    const float* bi  = (const float*)d_in[7];
    const float* we  = (const float*)d_in[8];
    const float* be  = (const float*)d_in[9];
    float* out = (float*)d_out;

    dim3 g1(BZ, 4, 1);
    k_dots<<<g1, 256>>>(emb, wh, wt, wi, we);
    k_main<<<BZ, 256>>>(msk, bh, bt, bi, be, out);
}

// round 2
// speedup vs baseline: 1.7178x; 1.7178x over previous
#include <cuda_runtime.h>
#include <cuda_bf16.h>
#include <math.h>

#define BZ 32
#define SZ 128
#define HZ 768
#define MM 8
#define MH_ 6
#define KK 4

// out layout (floats): implicit[0,512) explicit[512,2560) hs[2560,35328) ts[35328,68096)

__global__ __launch_bounds__(256, 1) void fused_opinion_kernel(
    const float* __restrict__ emb,
    const int* __restrict__ mask,
    const float* __restrict__ wh,
    const float* __restrict__ bh_,
    const float* __restrict__ wt,
    const float* __restrict__ bt_,
    const float* __restrict__ wi,
    const float* __restrict__ bi,
    const float* __restrict__ we,
    const float* __restrict__ be,
    float* __restrict__ out)
{
    __shared__ float pref[2][SZ + 1];        // [0]=wt (target), [1]=wh (holder)
    __shared__ float sc[2][MM * SZ];         // [0]=ts, [1]=hs
    __shared__ unsigned long long cand[2][16];
    __shared__ float topv[2][KK];
    __shared__ int   topi[2][KK];
    __shared__ float tdotI[KK][4];
    __shared__ float tdotE[KK][4];
    __shared__ float hdotE[KK][4];
    __shared__ int s_len;

    const int b = blockIdx.x;
    const int tid = threadIdx.x;
    const int warp = tid >> 5, lane = tid & 31;
    const float* eb = emb + (size_t)b * SZ * HZ;

    if (tid == 0) s_len = 0;
    if (tid < 2) pref[tid][0] = 0.f;
    __syncthreads();

    // sentence length (sum of mask)
    if (tid < SZ) {
        int v = mask[b * SZ + tid];
#pragma unroll
        for (int off = 16; off; off >>= 1) v += __shfl_xor_sync(0xFFFFFFFFu, v, off);
        if (lane == 0) atomicAdd(&s_len, v);
    }

    // ---------------- phase 1: per-row dots with wh, wt ----------------
    // warp handles 16 rows; batched float4 loads (24 LDG.128 in flight) for MLP.
    float4 wh4[6], wt4[6];
#pragma unroll
    for (int i = 0; i < 6; i++) {
        wh4[i] = ((const float4*)wh)[lane + 32 * i];
        wt4[i] = ((const float4*)wt)[lane + 32 * i];
    }
    const int r0 = warp * 16;
#pragma unroll 1
    for (int rb = 0; rb < 16; rb += 4) {
        float4 v[4][6];
#pragma unroll
        for (int r = 0; r < 4; r++) {
            const float4* rp = (const float4*)(eb + (size_t)(r0 + rb + r) * HZ);
#pragma unroll
            for (int i = 0; i < 6; i++) v[r][i] = rp[lane + 32 * i];
        }
#pragma unroll
        for (int r = 0; r < 4; r++) {
            float ah = 0.f, at = 0.f;
#pragma unroll
            for (int i = 0; i < 6; i++) {
                ah += v[r][i].x * wh4[i].x + v[r][i].y * wh4[i].y
                    + v[r][i].z * wh4[i].z + v[r][i].w * wh4[i].w;
                at += v[r][i].x * wt4[i].x + v[r][i].y * wt4[i].y
                    + v[r][i].z * wt4[i].z + v[r][i].w * wt4[i].w;
            }
#pragma unroll
            for (int off = 16; off; off >>= 1) {
                ah += __shfl_xor_sync(0xFFFFFFFFu, ah, off);
                at += __shfl_xor_sync(0xFFFFFFFFu, at, off);
            }
            if (lane == 0) {
                pref[0][r0 + rb + r + 1] = at;
                pref[1][r0 + rb + r + 1] = ah;
            }
        }
    }
    __syncthreads();

    // ---------------- phase 2: prefix sums over S (warps 0,1) ----------------
    if (warp < 2) {
        const int c = warp;
        float v0 = pref[c][lane * 4 + 1];
        float v1 = pref[c][lane * 4 + 2];
        float v2 = pref[c][lane * 4 + 3];
        float v3 = pref[c][lane * 4 + 4];
        v1 += v0; v2 += v1; v3 += v2;
        float tot = v3, x = tot;
#pragma unroll
        for (int off = 1; off < 32; off <<= 1) {
            float y = __shfl_up_sync(0xFFFFFFFFu, x, off);
            if (lane >= off) x += y;
        }
        float excl = x - tot;
        pref[c][lane * 4 + 1] = v0 + excl;
        pref[c][lane * 4 + 2] = v1 + excl;
        pref[c][lane * 4 + 3] = v2 + excl;
        pref[c][lane * 4 + 4] = v3 + excl;
    }
    __syncthreads();

    // ---------------- phase 3: span scores + hs/ts outputs ----------------
    const int len = s_len;
    const float btv = bt_[0], bhv = bh_[0];
    float* out_hs = out + 2560  + (size_t)b * (MM * SZ);
    float* out_ts = out + 35328 + (size_t)b * (MM * SZ);
#pragma unroll
    for (int i = 0; i < 4; i++) {
        int idx = tid + 256 * i;
        int m = idx >> 7, s = idx & 127;
        int e = s + m + 1; if (e > SZ) e = SZ;   // clamp (invalid anyway)
        float w = (float)(m + 1);
        bool tv = (s + m) < len;
        bool hv = tv && (m < MH_);
        float dt = (pref[0][e] - pref[0][s]) / w;
        float dh = (pref[1][e] - pref[1][s]) / w;
        float vt = tv ? 1.f / (1.f + expf(-(dt + btv))) : -1.f;
        float vh = hv ? 1.f / (1.f + expf(-(dh + bhv))) : -1.f;
        sc[0][idx] = vt; sc[1][idx] = vh;
        out_ts[idx] = vt; out_hs[idx] = vh;
    }
    __syncthreads();

    // ---------------- phase 4: single-pass top-4 (t: warps 0-3, h: warps 4-7) ----
    {
        const int type = warp >> 2;
        const int base = tid & 127;
        unsigned long long t4[4] = {0ull, 0ull, 0ull, 0ull};
#pragma unroll
        for (int i = 0; i < 8; i++) {
            int idx = base + 128 * i;
            unsigned u = __float_as_uint(sc[type][idx]);
            u = (u & 0x80000000u) ? ~u : (u | 0x80000000u);
            unsigned long long key =
                ((unsigned long long)u << 32) | (unsigned)(0xFFFFFFFFu - idx);
            if (key > t4[0])      { t4[3]=t4[2]; t4[2]=t4[1]; t4[1]=t4[0]; t4[0]=key; }
            else if (key > t4[1]) { t4[3]=t4[2]; t4[2]=t4[1]; t4[1]=key; }
            else if (key > t4[2]) { t4[3]=t4[2]; t4[2]=key; }
            else if (key > t4[3]) { t4[3]=key; }
        }
        // butterfly merge of sorted-4 lists
#pragma unroll
        for (int off = 16; off; off >>= 1) {
            unsigned long long o[4];
#pragma unroll
            for (int j = 0; j < 4; j++) o[j] = __shfl_xor_sync(0xFFFFFFFFu, t4[j], off);
            unsigned long long mrg[4];
            int ai = 0, bi2 = 0;
#pragma unroll
            for (int m = 0; m < 4; m++)
                mrg[m] = (t4[ai] >= o[bi2]) ? t4[ai++] : o[bi2++];
#pragma unroll
            for (int j = 0; j < 4; j++) t4[j] = mrg[j];
        }
        if (lane == 0) {
            int wq = warp & 3;
#pragma unroll
            for (int j = 0; j < 4; j++) cand[type][wq * 4 + j] = t4[j];
        }
    }
    __syncthreads();

    if (lane == 0 && (warp == 0 || warp == 4)) {
        const int type = warp >> 2;
        unsigned long long c16[16];
#pragma unroll
        for (int j = 0; j < 16; j++) c16[j] = cand[type][j];
#pragma unroll
        for (int k = 0; k < KK; k++) {
            unsigned long long best = 0ull; int bj = 0;
#pragma unroll
            for (int j = 0; j < 16; j++)
                if (c16[j] > best) { best = c16[j]; bj = j; }
            c16[bj] = 0ull;
            unsigned hi = (unsigned)(best >> 32);
            unsigned lo = (unsigned)best;
            float v = (hi & 0x80000000u) ? __uint_as_float(hi ^ 0x80000000u)
                                         : __uint_as_float(~hi);
            topv[type][k] = v;
            topi[type][k] = (int)(0xFFFFFFFFu - lo);
        }
    }
    __syncthreads();

    // ---------------- phase 5: rep dots for selected spans (1 warp per span) ----
    {
        const int type = warp >> 2;      // 0 = target, 1 = holder
        const int k = warp & 3;
        const int idx = topi[type][k];
        const bool valid = topv[type][k] > 0.f;
        const int m = idx >> 7, s = idx & 127;
        const float inv = 1.f / (float)(m + 1);
        float acc[8] = {0.f,0.f,0.f,0.f,0.f,0.f,0.f,0.f};
        if (valid) {
#pragma unroll 1
            for (int i = 0; i < 6; i++) {
                int h4 = lane + 32 * i;
                float4 sum = make_float4(0.f, 0.f, 0.f, 0.f);
                for (int r = 0; r <= m; r++) {
                    float4 v = ((const float4*)(eb + (size_t)(s + r) * HZ))[h4];
                    sum.x += v.x; sum.y += v.y; sum.z += v.z; sum.w += v.w;
                }
                sum.x *= inv; sum.y *= inv; sum.z *= inv; sum.w *= inv;
                const float* sp = &sum.x;
                if (type == 0) {
#pragma unroll
                    for (int c = 0; c < 4; c++) {
                        float sv = sp[c];
                        float4 wv = ((const float4*)wi)[4 * h4 + c];
                        acc[0] += sv * wv.x; acc[1] += sv * wv.y;
                        acc[2] += sv * wv.z; acc[3] += sv * wv.w;
                        float4 ev = ((const float4*)we)[HZ + 4 * h4 + c];
                        acc[4] += sv * ev.x; acc[5] += sv * ev.y;
                        acc[6] += sv * ev.z; acc[7] += sv * ev.w;
                    }
                } else {
#pragma unroll
                    for (int c = 0; c < 4; c++) {
                        float sv = sp[c];
                        float4 ev = ((const float4*)we)[4 * h4 + c];
                        acc[0] += sv * ev.x; acc[1] += sv * ev.y;
                        acc[2] += sv * ev.z; acc[3] += sv * ev.w;
                    }
                }
            }
        }
#pragma unroll
        for (int j = 0; j < 8; j++)
#pragma unroll
            for (int off = 16; off; off >>= 1)
                acc[j] += __shfl_xor_sync(0xFFFFFFFFu, acc[j], off);
        if (lane == 0) {
            if (type == 0) {
#pragma unroll
                for (int j = 0; j < 4; j++) { tdotI[k][j] = acc[j]; tdotE[k][j] = acc[4 + j]; }
            } else {
#pragma unroll
                for (int j = 0; j < 4; j++) hdotE[k][j] = acc[j];
            }
        }
    }
    __syncthreads();

    // ---------------- phase 6: logits ----------------
    if (tid < 64) {
        int k = tid >> 4, i = (tid >> 2) & 3, j = tid & 3;
        bool pv = (topv[1][k] > 0.f) && (topv[0][i] > 0.f);
        float val = be[j] + (pv ? (hdotE[k][j] + tdotE[i][j]) : 0.f);
        out[512 + (size_t)b * 64 + tid] = val;
    } else if (tid < 80) {
        int t2 = tid - 64;
        int i = t2 >> 2, j = t2 & 3;
        float val = bi[j] + ((topv[0][i] > 0.f) ? tdotI[i][j] : 0.f);
        out[(size_t)b * 16 + t2] = val;
    }
}

extern "C" void kernel_launch(void* const* d_in, const int* in_sizes, int n_in,
                              void* d_out, int out_size)
{
    const float* emb = (const float*)d_in[0];
    const int*   msk = (const int*)d_in[1];
    const float* wh  = (const float*)d_in[2];
    const float* bh  = (const float*)d_in[3];
    const float* wt  = (const float*)d_in[4];
    const float* bt  = (const float*)d_in[5];
    const float* wi  = (const float*)d_in[6];
    const float* bi  = (const float*)d_in[7];
    const float* we  = (const float*)d_in[8];
    const float* be  = (const float*)d_in[9];
    float* out = (float*)d_out;

    fused_opinion_kernel<<<BZ, 256>>>(emb, msk, wh, bh, wt, bt, wi, bi, we, be, out);
}